// round 9
// baseline (speedup 1.0000x reference)
#include <cuda_runtime.h>
#include <cuda_bf16.h>
#include <cstdint>

// ---------------- problem constants ----------------
#define B_        8
#define S_        1024
#define D_        4096
#define DV_       1024
#define IMG_      336
#define PATCH_    14
#define GRID_     24
#define NP_       576
#define MAXE_     1599
#define KPATCH_   588
#define M_        (B_*NP_)    // 4608
#define IMAGE_TOKEN_ 32000

#define OFF_EMB   1LL
#define N_EMB     ((long long)B_*MAXE_*D_)
#define OFF_ATTN  (OFF_EMB + N_EMB)
#define OFF_LAB   (OFF_ATTN + (long long)B_*MAXE_)
#define OFF_ROUT  (OFF_LAB  + (long long)B_*MAXE_)
#define N_TAIL    (32LL*MAXE_*8 + 32LL*MAXE_*2)

// ---------------- device scratch (fp32 only — validated pattern) ----------------
__device__ float g_h[(size_t)M_ * DV_];   // patch-embed output
__device__ float g_g[(size_t)M_ * D_];    // gelu output
__device__ int   g_spos[B_];

__device__ __forceinline__ float gelu_tanh(float x) {
    float x3 = x * x * x;
    return 0.5f * x * (1.0f + tanhf(0.7978845608028654f * (x + 0.044715f * x3)));
}

__device__ __forceinline__ uint32_t s2u(const void* p) {
    return (uint32_t)__cvta_generic_to_shared(p);
}
__device__ __forceinline__ void ldmx4(uint32_t* r, uint32_t addr) {
    asm volatile("ldmatrix.sync.aligned.m8n8.x4.shared.b16 {%0,%1,%2,%3}, [%4];"
                 : "=r"(r[0]), "=r"(r[1]), "=r"(r[2]), "=r"(r[3]) : "r"(addr) : "memory");
}
__device__ __forceinline__ void ldmx4t(uint32_t* r, uint32_t addr) {
    asm volatile("ldmatrix.sync.aligned.m8n8.x4.trans.shared.b16 {%0,%1,%2,%3}, [%4];"
                 : "=r"(r[0]), "=r"(r[1]), "=r"(r[2]), "=r"(r[3]) : "r"(addr) : "memory");
}
__device__ __forceinline__ void mma_bf16(float* c, const uint32_t* a, const uint32_t* b) {
    asm volatile(
        "mma.sync.aligned.m16n8k16.row.col.f32.bf16.bf16.f32 "
        "{%0,%1,%2,%3}, {%4,%5,%6,%7}, {%8,%9}, {%0,%1,%2,%3};"
        : "+f"(c[0]), "+f"(c[1]), "+f"(c[2]), "+f"(c[3])
        : "r"(a[0]), "r"(a[1]), "r"(a[2]), "r"(a[3]), "r"(b[0]), "r"(b[1]));
}
__device__ __forceinline__ uint32_t ph(int row) { return ((row >> 2) & 1) << 4; }

// split 8 fp32 -> 8 bf16 hi + 8 bf16 lo (packed uint4 each)
__device__ __forceinline__ void split8(const float* f, uint4& h4, uint4& l4) {
    uint32_t hw[4], lw[4];
    #pragma unroll
    for (int i = 0; i < 4; i++) {
        __nv_bfloat16 h0 = __float2bfloat16(f[2*i]);
        __nv_bfloat16 h1 = __float2bfloat16(f[2*i+1]);
        __nv_bfloat16 l0 = __float2bfloat16(f[2*i]   - __bfloat162float(h0));
        __nv_bfloat16 l1 = __float2bfloat16(f[2*i+1] - __bfloat162float(h1));
        __nv_bfloat162 hp; hp.x = h0; hp.y = h1;
        __nv_bfloat162 lp; lp.x = l0; lp.y = l1;
        hw[i] = *(uint32_t*)&hp;
        lw[i] = *(uint32_t*)&lp;
    }
    h4 = make_uint4(hw[0], hw[1], hw[2], hw[3]);
    l4 = make_uint4(lw[0], lw[1], lw[2], lw[3]);
}

// ---------------- small kernels (R1-proven) ----------------
__global__ void k_fill(float* __restrict__ out) {
    long long i = (long long)blockIdx.x * blockDim.x + threadIdx.x;
    if (i == 0) out[0] = 0.0f;
    if (i < B_) g_spos[i] = S_;
    long long stride = (long long)gridDim.x * blockDim.x;
    for (long long j = i; j < N_TAIL; j += stride)
        out[OFF_ROUT + j] = 0.0f;
}

__global__ void k_spos(const int* __restrict__ ids) {
    int i = blockIdx.x * blockDim.x + threadIdx.x;
    if (i < B_ * S_ && ids[i] == IMAGE_TOKEN_)
        atomicMin(&g_spos[i / S_], i % S_);
}

__global__ void k_text(const int* __restrict__ ids, const int* __restrict__ mask,
                       const int* __restrict__ labels, const float* __restrict__ table,
                       float* __restrict__ out) {
    int bs = blockIdx.x;
    int b = bs / S_, s = bs - b * S_;
    int id = ids[bs];
    if (id == IMAGE_TOKEN_) return;
    int sp = g_spos[b];
    int dest = s + (s > sp ? (NP_ - 1) : 0);
    const float* __restrict__ src = table + (long long)id * D_;
    float* __restrict__ dst = out + OFF_EMB + ((long long)b * MAXE_ + dest) * D_;
    for (int j = threadIdx.x; j < D_; j += blockDim.x)
        dst[j] = src[j];
    if (threadIdx.x == 0) {
        out[OFF_ATTN + (long long)b * MAXE_ + dest] = (float)mask[bs];
        out[OFF_LAB  + (long long)b * MAXE_ + dest] = (float)labels[bs];
    }
}

__global__ void k_imgmeta(float* __restrict__ out) {
    int i = blockIdx.x * blockDim.x + threadIdx.x;
    if (i >= B_ * NP_) return;
    int b = i / NP_, t = i - b * NP_;
    int dest = g_spos[b] + t;
    out[OFF_ATTN + (long long)b * MAXE_ + dest] = 1.0f;
    out[OFF_LAB  + (long long)b * MAXE_ + dest] = -100.0f;
}

// ---------------- patch-embed GEMM (R1-proven, fp32) ----------------
__global__ void __launch_bounds__(256)
k_patch(const float* __restrict__ pix, const float* __restrict__ Bw,
        const float* __restrict__ bias) {
    __shared__ float As[16][132];
    __shared__ float Bs[16][132];
    int t  = threadIdx.x;
    int m0 = blockIdx.y * 128;
    int n0 = blockIdx.x * 128;
    float acc[8][8] = {};
    int brow = t >> 5, bcol = t & 31;
    int rm = (t >> 4) * 8, rn = (t & 15) * 8;

    for (int k0 = 0; k0 < KPATCH_; k0 += 16) {
        #pragma unroll
        for (int i = 0; i < 8; i++) {
            int idx = t + 256 * i;
            int r  = idx >> 4;
            int kk = idx & 15;
            int k  = k0 + kk;
            float v = 0.0f;
            if (k < KPATCH_) {
                int m  = m0 + r;
                int ni = m / NP_;
                int tt = m - ni * NP_;
                int gi = tt / GRID_, gj = tt - gi * GRID_;
                int c  = k / 196;
                int rem = k - c * 196;
                int pi = rem / PATCH_, pj = rem - pi * PATCH_;
                long long addr = (((long long)ni * 3 + c) * IMG_ + gi * PATCH_ + pi) * IMG_
                               + gj * PATCH_ + pj;
                v = pix[addr];
            }
            As[kk][r] = v;
        }
        #pragma unroll
        for (int i = 0; i < 2; i++) {
            int kk = brow + i * 8;
            int k  = k0 + kk;
            float4 v = make_float4(0.f, 0.f, 0.f, 0.f);
            if (k < KPATCH_)
                v = *(const float4*)(Bw + (long long)k * DV_ + n0 + bcol * 4);
            *(float4*)(&Bs[kk][bcol * 4]) = v;
        }
        __syncthreads();
        #pragma unroll
        for (int k = 0; k < 16; k++) {
            float ra[8], rb[8];
            #pragma unroll
            for (int i = 0; i < 8; i++) ra[i] = As[k][rm + i];
            #pragma unroll
            for (int j = 0; j < 8; j++) rb[j] = Bs[k][rn + j];
            #pragma unroll
            for (int i = 0; i < 8; i++)
                #pragma unroll
                for (int j = 0; j < 8; j++)
                    acc[i][j] += ra[i] * rb[j];
        }
        __syncthreads();
    }
    #pragma unroll
    for (int i = 0; i < 8; i++) {
        int m = m0 + rm + i;
        #pragma unroll
        for (int j = 0; j < 8; j++) {
            int n = n0 + rn + j;
            g_h[(size_t)m * DV_ + n] = acc[i][j] + bias[n];
        }
    }
}

// ---------------- TC GEMM — double-buffered (R8 recipe + 2-stage pipeline) ----------------
// fp32 sources, in-kernel bf16 split, plain global loads, 48KB static smem (2 stages),
// ONE __syncthreads per chunk: stores go to the idle buffer during compute.
// CTA 128(M) x 256(N), K-chunk 16, 8 warps 2x4, warp tile 64x64.
template<int EPI>
__global__ void __launch_bounds__(256)
k_tc(const float* __restrict__ W, const float* __restrict__ bias,
     float* __restrict__ out) {
    constexpr int K = (EPI == 1) ? DV_ : D_;
    const float* __restrict__ A = (EPI == 1) ? g_h : g_g;

    __shared__ __align__(16) char sa[2][2][4096];  // [stage][hi/lo] A: 128 rows x 32B
    __shared__ __align__(16) char sb[2][2][8192];  // [stage][hi/lo] B: 16 k-rows x 512B

    const int t = threadIdx.x, l = t & 31, wid = t >> 5;
    const int wm = wid >> 2, wn = wid & 3;
    const int m0 = blockIdx.y * 128;
    const int n0 = blockIdx.x * 256;

    float acc[4][8][4] = {};

    // register staging
    const int arow = t >> 1, ahalf = t & 1;
    float ra[8], rb[2][8];

    auto ldregs = [&](int kc) {
        const float* ap = A + (size_t)(m0 + arow) * K + kc + ahalf * 8;
        float4 x = *(const float4*)ap;
        float4 y = *(const float4*)(ap + 4);
        ra[0]=x.x; ra[1]=x.y; ra[2]=x.z; ra[3]=x.w;
        ra[4]=y.x; ra[5]=y.y; ra[6]=y.z; ra[7]=y.w;
        #pragma unroll
        for (int i = 0; i < 2; i++) {
            int idx = t + 256 * i;
            int k = idx >> 5, seg = idx & 31;
            const float* bp = W + (size_t)(kc + k) * D_ + n0 + seg * 8;
            float4 u = *(const float4*)bp;
            float4 v = *(const float4*)(bp + 4);
            rb[i][0]=u.x; rb[i][1]=u.y; rb[i][2]=u.z; rb[i][3]=u.w;
            rb[i][4]=v.x; rb[i][5]=v.y; rb[i][6]=v.z; rb[i][7]=v.w;
        }
    };
    auto stregs = [&](int st) {
        uint4 h4, l4;
        split8(ra, h4, l4);
        uint32_t off = arow * 32 + ((ahalf * 16) ^ ph(arow));
        *(uint4*)(sa[st][0] + off) = h4;
        *(uint4*)(sa[st][1] + off) = l4;
        #pragma unroll
        for (int i = 0; i < 2; i++) {
            int idx = t + 256 * i;
            int k = idx >> 5, seg = idx & 31;
            split8(rb[i], h4, l4);
            uint32_t o2 = k * 512 + ((seg * 16) ^ ((k & 7) * 16));
            *(uint4*)(sb[st][0] + o2) = h4;
            *(uint4*)(sb[st][1] + o2) = l4;
        }
    };

    const int frow = l & 15, kb = ((l >> 4) & 1) * 16;
    const int bg = l >> 3, br = l & 7;
    const int bk = (bg & 1) * 8 + br;
    const int bnb = (bg >> 1) * 8;

    auto compute = [&](int st) {
        uint32_t ah[4][4], al[4][4];
        #pragma unroll
        for (int mi = 0; mi < 4; mi++) {
            int row = wm * 64 + mi * 16 + frow;
            uint32_t off = row * 32 + (kb ^ ph(row));
            ldmx4(ah[mi], s2u(sa[st][0]) + off);
            ldmx4(al[mi], s2u(sa[st][1]) + off);
        }
        #pragma unroll
        for (int p = 0; p < 4; p++) {
            int nb = wn * 64 + p * 16 + bnb;
            uint32_t o = bk * 512 + ((nb * 2) ^ ((bk & 7) * 16));
            uint32_t rh[4], rl[4];
            ldmx4t(rh, s2u(sb[st][0]) + o);
            ldmx4t(rl, s2u(sb[st][1]) + o);
            uint32_t b0h[2] = { rh[0], rh[1] }, b1h[2] = { rh[2], rh[3] };
            uint32_t b0l[2] = { rl[0], rl[1] }, b1l[2] = { rl[2], rl[3] };
            #pragma unroll
            for (int mi = 0; mi < 4; mi++) {
                mma_bf16(acc[mi][2*p],   ah[mi], b0h);
                mma_bf16(acc[mi][2*p],   ah[mi], b0l);
                mma_bf16(acc[mi][2*p],   al[mi], b0h);
                mma_bf16(acc[mi][2*p+1], ah[mi], b1h);
                mma_bf16(acc[mi][2*p+1], ah[mi], b1l);
                mma_bf16(acc[mi][2*p+1], al[mi], b1h);
            }
        }
    };

    const int nch = K / 16;   // 64 or 256, always >= 2
    // pipeline prologue: buf0 filled, chunk1 in regs
    ldregs(0);
    stregs(0);
    ldregs(16);
    // steady state: one sync per chunk
    for (int c = 0; c < nch; c++) {
        __syncthreads();                       // buf c&1 ready; prior readers of buf (c+1)&1 done
        if (c + 1 < nch) stregs((c + 1) & 1);  // fill idle buffer from regs (chunk c+1)
        if (c + 2 < nch) ldregs((c + 2) * 16); // prefetch chunk c+2 into regs
        compute(c & 1);
    }

    // epilogue — EPI==2 rows start at OFF_EMB=1 (odd float offset): scalar stores only.
    const int lrow = l >> 2, lcol = (l & 3) * 2;
    #pragma unroll
    for (int mi = 0; mi < 4; mi++) {
        #pragma unroll
        for (int part = 0; part < 2; part++) {
            int m = m0 + wm * 64 + mi * 16 + lrow + part * 8;
            long long rowbase;
            if (EPI == 2) {
                int bb = m / NP_;
                int tt = m - bb * NP_;
                rowbase = OFF_EMB + ((long long)bb * MAXE_ + g_spos[bb] + tt) * (long long)D_;
            } else {
                rowbase = (long long)m * D_;
            }
            #pragma unroll
            for (int nj = 0; nj < 8; nj++) {
                int n = n0 + wn * 64 + nj * 8 + lcol;
                float v0 = acc[mi][nj][part * 2 + 0] + bias[n];
                float v1 = acc[mi][nj][part * 2 + 1] + bias[n + 1];
                if (EPI == 1) {
                    float2 gg = make_float2(gelu_tanh(v0), gelu_tanh(v1));
                    *(float2*)&g_g[rowbase + n] = gg;
                } else {
                    out[rowbase + n]     = v0;
                    out[rowbase + n + 1] = v1;
                }
            }
        }
    }
}

// ---------------- launch ----------------
extern "C" void kernel_launch(void* const* d_in, const int* in_sizes, int n_in,
                              void* d_out, int out_size) {
    const int*   ids     = (const int*)  d_in[0];
    const float* pix     = (const float*)d_in[1];
    const int*   mask    = (const int*)  d_in[2];
    const int*   labels  = (const int*)  d_in[3];
    const float* table   = (const float*)d_in[4];
    const float* patch_w = (const float*)d_in[6];
    const float* patch_b = (const float*)d_in[7];
    const float* w1      = (const float*)d_in[8];
    const float* b1      = (const float*)d_in[9];
    const float* w2      = (const float*)d_in[10];
    const float* b2      = (const float*)d_in[11];
    float* out = (float*)d_out;

    k_fill<<<512, 256>>>(out);
    k_spos<<<(B_ * S_ + 255) / 256, 256>>>(ids);
    k_text<<<B_ * S_, 256>>>(ids, mask, labels, table, out);
    k_imgmeta<<<(B_ * NP_ + 255) / 256, 256>>>(out);

    k_patch<<<dim3(DV_ / 128, M_ / 128), 256>>>(pix, patch_w, patch_b);
    k_tc<1><<<dim3(D_ / 256, M_ / 128), 256>>>(w1, b1, out);
    k_tc<2><<<dim3(D_ / 256, M_ / 128), 256>>>(w2, b2, out);
}

// round 10
// speedup vs baseline: 1.0747x; 1.0747x over previous
#include <cuda_runtime.h>
#include <cuda_bf16.h>
#include <cstdint>

// ---------------- problem constants ----------------
#define B_        8
#define S_        1024
#define D_        4096
#define DV_       1024
#define IMG_      336
#define PATCH_    14
#define GRID_     24
#define NP_       576
#define MAXE_     1599
#define KPATCH_   588
#define M_        (B_*NP_)    // 4608
#define IMAGE_TOKEN_ 32000

#define OFF_EMB   1LL
#define N_EMB     ((long long)B_*MAXE_*D_)
#define OFF_ATTN  (OFF_EMB + N_EMB)
#define OFF_LAB   (OFF_ATTN + (long long)B_*MAXE_)
#define OFF_ROUT  (OFF_LAB  + (long long)B_*MAXE_)
#define N_TAIL    (32LL*MAXE_*8 + 32LL*MAXE_*2)

// ---------------- device scratch (fp32 only — validated pattern) ----------------
__device__ float g_h[(size_t)M_ * DV_];   // patch-embed output
__device__ float g_g[(size_t)M_ * D_];    // gelu output
__device__ int   g_spos[B_];

__device__ __forceinline__ float gelu_tanh(float x) {
    float x3 = x * x * x;
    return 0.5f * x * (1.0f + tanhf(0.7978845608028654f * (x + 0.044715f * x3)));
}

__device__ __forceinline__ uint32_t f2tf(float f) {
    uint32_t u;
    asm("cvt.rna.tf32.f32 %0, %1;" : "=r"(u) : "f"(f));
    return u;
}
__device__ __forceinline__ void mma_tf32(float* c, const uint32_t* a, const uint32_t* b) {
    asm volatile(
        "mma.sync.aligned.m16n8k8.row.col.f32.tf32.tf32.f32 "
        "{%0,%1,%2,%3}, {%4,%5,%6,%7}, {%8,%9}, {%0,%1,%2,%3};"
        : "+f"(c[0]), "+f"(c[1]), "+f"(c[2]), "+f"(c[3])
        : "r"(a[0]), "r"(a[1]), "r"(a[2]), "r"(a[3]), "r"(b[0]), "r"(b[1]));
}

// ---------------- small kernels (R1-proven) ----------------
__global__ void k_fill(float* __restrict__ out) {
    long long i = (long long)blockIdx.x * blockDim.x + threadIdx.x;
    if (i == 0) out[0] = 0.0f;
    if (i < B_) g_spos[i] = S_;
    long long stride = (long long)gridDim.x * blockDim.x;
    for (long long j = i; j < N_TAIL; j += stride)
        out[OFF_ROUT + j] = 0.0f;
}

__global__ void k_spos(const int* __restrict__ ids) {
    int i = blockIdx.x * blockDim.x + threadIdx.x;
    if (i < B_ * S_ && ids[i] == IMAGE_TOKEN_)
        atomicMin(&g_spos[i / S_], i % S_);
}

__global__ void k_text(const int* __restrict__ ids, const int* __restrict__ mask,
                       const int* __restrict__ labels, const float* __restrict__ table,
                       float* __restrict__ out) {
    int bs = blockIdx.x;
    int b = bs / S_, s = bs - b * S_;
    int id = ids[bs];
    if (id == IMAGE_TOKEN_) return;
    int sp = g_spos[b];
    int dest = s + (s > sp ? (NP_ - 1) : 0);
    const float* __restrict__ src = table + (long long)id * D_;
    float* __restrict__ dst = out + OFF_EMB + ((long long)b * MAXE_ + dest) * D_;
    for (int j = threadIdx.x; j < D_; j += blockDim.x)
        dst[j] = src[j];
    if (threadIdx.x == 0) {
        out[OFF_ATTN + (long long)b * MAXE_ + dest] = (float)mask[bs];
        out[OFF_LAB  + (long long)b * MAXE_ + dest] = (float)labels[bs];
    }
}

__global__ void k_imgmeta(float* __restrict__ out) {
    int i = blockIdx.x * blockDim.x + threadIdx.x;
    if (i >= B_ * NP_) return;
    int b = i / NP_, t = i - b * NP_;
    int dest = g_spos[b] + t;
    out[OFF_ATTN + (long long)b * MAXE_ + dest] = 1.0f;
    out[OFF_LAB  + (long long)b * MAXE_ + dest] = -100.0f;
}

// ---------------- patch-embed GEMM (R1-proven, fp32) ----------------
__global__ void __launch_bounds__(256)
k_patch(const float* __restrict__ pix, const float* __restrict__ Bw,
        const float* __restrict__ bias) {
    __shared__ float As[16][132];
    __shared__ float Bs[16][132];
    int t  = threadIdx.x;
    int m0 = blockIdx.y * 128;
    int n0 = blockIdx.x * 128;
    float acc[8][8] = {};
    int brow = t >> 5, bcol = t & 31;
    int rm = (t >> 4) * 8, rn = (t & 15) * 8;

    for (int k0 = 0; k0 < KPATCH_; k0 += 16) {
        #pragma unroll
        for (int i = 0; i < 8; i++) {
            int idx = t + 256 * i;
            int r  = idx >> 4;
            int kk = idx & 15;
            int k  = k0 + kk;
            float v = 0.0f;
            if (k < KPATCH_) {
                int m  = m0 + r;
                int ni = m / NP_;
                int tt = m - ni * NP_;
                int gi = tt / GRID_, gj = tt - gi * GRID_;
                int c  = k / 196;
                int rem = k - c * 196;
                int pi = rem / PATCH_, pj = rem - pi * PATCH_;
                long long addr = (((long long)ni * 3 + c) * IMG_ + gi * PATCH_ + pi) * IMG_
                               + gj * PATCH_ + pj;
                v = pix[addr];
            }
            As[kk][r] = v;
        }
        #pragma unroll
        for (int i = 0; i < 2; i++) {
            int kk = brow + i * 8;
            int k  = k0 + kk;
            float4 v = make_float4(0.f, 0.f, 0.f, 0.f);
            if (k < KPATCH_)
                v = *(const float4*)(Bw + (long long)k * DV_ + n0 + bcol * 4);
            *(float4*)(&Bs[kk][bcol * 4]) = v;
        }
        __syncthreads();
        #pragma unroll
        for (int k = 0; k < 16; k++) {
            float ra[8], rb[8];
            #pragma unroll
            for (int i = 0; i < 8; i++) ra[i] = As[k][rm + i];
            #pragma unroll
            for (int j = 0; j < 8; j++) rb[j] = Bs[k][rn + j];
            #pragma unroll
            for (int i = 0; i < 8; i++)
                #pragma unroll
                for (int j = 0; j < 8; j++)
                    acc[i][j] += ra[i] * rb[j];
        }
        __syncthreads();
    }
    #pragma unroll
    for (int i = 0; i < 8; i++) {
        int m = m0 + rm + i;
        #pragma unroll
        for (int j = 0; j < 8; j++) {
            int n = n0 + rn + j;
            g_h[(size_t)m * DV_ + n] = acc[i][j] + bias[n];
        }
    }
}

// ---------------- TC GEMM — single-pass TF32 (R8 pipeline structure) ----------------
// fp32 sources, cvt.rna.tf32 in-kernel, plain global loads, single-buffer smem,
// register prefetch. CTA 128(M) x 256(N), K-chunk 16 (2 x k8 MMA steps),
// 8 warps 2x4, warp tile 64x64, mma.m16n8k8.tf32.
// sA: 128 rows x 20 floats (pad) — conflict-free fragment loads.
// sB: 16 k-rows x 264 floats (pad) — conflict-free fragment loads.
#define SAPITCH 20
#define SBPITCH 264

template<int EPI>
__global__ void __launch_bounds__(256)
k_tc(const float* __restrict__ W, const float* __restrict__ bias,
     float* __restrict__ out) {
    constexpr int K = (EPI == 1) ? DV_ : D_;
    const float* __restrict__ A = (EPI == 1) ? g_h : g_g;

    __shared__ __align__(16) uint32_t sA[128 * SAPITCH];   // 10240 B
    __shared__ __align__(16) uint32_t sB[16 * SBPITCH];    // 16896 B

    const int t = threadIdx.x, l = t & 31, wid = t >> 5;
    const int wm = wid >> 2, wn = wid & 3;
    const int m0 = blockIdx.y * 128;
    const int n0 = blockIdx.x * 256;

    float acc[4][8][4] = {};

    // register staging (R8-proven shape)
    const int arow = t >> 1, ahalf = t & 1;
    float ra[8], rb[2][8];

    auto ldregs = [&](int kc) {
        const float* ap = A + (size_t)(m0 + arow) * K + kc + ahalf * 8;
        float4 x = *(const float4*)ap;
        float4 y = *(const float4*)(ap + 4);
        ra[0]=x.x; ra[1]=x.y; ra[2]=x.z; ra[3]=x.w;
        ra[4]=y.x; ra[5]=y.y; ra[6]=y.z; ra[7]=y.w;
        #pragma unroll
        for (int i = 0; i < 2; i++) {
            int idx = t + 256 * i;
            int k = idx >> 5, seg = idx & 31;
            const float* bp = W + (size_t)(kc + k) * D_ + n0 + seg * 8;
            float4 u = *(const float4*)bp;
            float4 v = *(const float4*)(bp + 4);
            rb[i][0]=u.x; rb[i][1]=u.y; rb[i][2]=u.z; rb[i][3]=u.w;
            rb[i][4]=v.x; rb[i][5]=v.y; rb[i][6]=v.z; rb[i][7]=v.w;
        }
    };
    auto stregs = [&]() {
        uint4 v0 = make_uint4(f2tf(ra[0]), f2tf(ra[1]), f2tf(ra[2]), f2tf(ra[3]));
        uint4 v1 = make_uint4(f2tf(ra[4]), f2tf(ra[5]), f2tf(ra[6]), f2tf(ra[7]));
        uint32_t ao = arow * SAPITCH + ahalf * 8;
        *(uint4*)&sA[ao]     = v0;
        *(uint4*)&sA[ao + 4] = v1;
        #pragma unroll
        for (int i = 0; i < 2; i++) {
            int idx = t + 256 * i;
            int k = idx >> 5, seg = idx & 31;
            uint4 w0 = make_uint4(f2tf(rb[i][0]), f2tf(rb[i][1]), f2tf(rb[i][2]), f2tf(rb[i][3]));
            uint4 w1 = make_uint4(f2tf(rb[i][4]), f2tf(rb[i][5]), f2tf(rb[i][6]), f2tf(rb[i][7]));
            uint32_t bo = k * SBPITCH + seg * 8;
            *(uint4*)&sB[bo]     = w0;
            *(uint4*)&sB[bo + 4] = w1;
        }
    };

    const int g = l >> 2, tg = l & 3;

    auto compute = [&]() {
        #pragma unroll
        for (int ks = 0; ks < 2; ks++) {
            uint32_t afr[4][4];
            #pragma unroll
            for (int mi = 0; mi < 4; mi++) {
                int rb0 = wm * 64 + mi * 16;
                afr[mi][0] = sA[(rb0 + g)     * SAPITCH + ks * 8 + tg];
                afr[mi][1] = sA[(rb0 + g + 8) * SAPITCH + ks * 8 + tg];
                afr[mi][2] = sA[(rb0 + g)     * SAPITCH + ks * 8 + tg + 4];
                afr[mi][3] = sA[(rb0 + g + 8) * SAPITCH + ks * 8 + tg + 4];
            }
            #pragma unroll
            for (int p = 0; p < 8; p++) {
                uint32_t bfr[2];
                int n = wn * 64 + p * 8 + g;
                bfr[0] = sB[(ks * 8 + tg)     * SBPITCH + n];
                bfr[1] = sB[(ks * 8 + tg + 4) * SBPITCH + n];
                #pragma unroll
                for (int mi = 0; mi < 4; mi++)
                    mma_tf32(acc[mi][p], afr[mi], bfr);
            }
        }
    };

    const int nch = K / 16;
    ldregs(0);
    for (int c = 0; c < nch; c++) {
        stregs();
        __syncthreads();
        if (c + 1 < nch) ldregs((c + 1) * 16);
        compute();
        __syncthreads();
    }

    // epilogue — EPI==2 rows start at OFF_EMB=1 (odd float offset): scalar stores only.
    const int lrow = l >> 2, lcol = (l & 3) * 2;
    #pragma unroll
    for (int mi = 0; mi < 4; mi++) {
        #pragma unroll
        for (int part = 0; part < 2; part++) {
            int m = m0 + wm * 64 + mi * 16 + lrow + part * 8;
            long long rowbase;
            if (EPI == 2) {
                int bb = m / NP_;
                int tt = m - bb * NP_;
                rowbase = OFF_EMB + ((long long)bb * MAXE_ + g_spos[bb] + tt) * (long long)D_;
            } else {
                rowbase = (long long)m * D_;
            }
            #pragma unroll
            for (int nj = 0; nj < 8; nj++) {
                int n = n0 + wn * 64 + nj * 8 + lcol;
                float v0 = acc[mi][nj][part * 2 + 0] + bias[n];
                float v1 = acc[mi][nj][part * 2 + 1] + bias[n + 1];
                if (EPI == 1) {
                    float2 gg = make_float2(gelu_tanh(v0), gelu_tanh(v1));
                    *(float2*)&g_g[rowbase + n] = gg;
                } else {
                    out[rowbase + n]     = v0;
                    out[rowbase + n + 1] = v1;
                }
            }
        }
    }
}

// ---------------- launch ----------------
extern "C" void kernel_launch(void* const* d_in, const int* in_sizes, int n_in,
                              void* d_out, int out_size) {
    const int*   ids     = (const int*)  d_in[0];
    const float* pix     = (const float*)d_in[1];
    const int*   mask    = (const int*)  d_in[2];
    const int*   labels  = (const int*)  d_in[3];
    const float* table   = (const float*)d_in[4];
    const float* patch_w = (const float*)d_in[6];
    const float* patch_b = (const float*)d_in[7];
    const float* w1      = (const float*)d_in[8];
    const float* b1      = (const float*)d_in[9];
    const float* w2      = (const float*)d_in[10];
    const float* b2      = (const float*)d_in[11];
    float* out = (float*)d_out;

    k_fill<<<512, 256>>>(out);
    k_spos<<<(B_ * S_ + 255) / 256, 256>>>(ids);
    k_text<<<B_ * S_, 256>>>(ids, mask, labels, table, out);
    k_imgmeta<<<(B_ * NP_ + 255) / 256, 256>>>(out);

    k_patch<<<dim3(DV_ / 128, M_ / 128), 256>>>(pix, patch_w, patch_b);
    k_tc<1><<<dim3(D_ / 256, M_ / 128), 256>>>(w1, b1, out);
    k_tc<2><<<dim3(D_ / 256, M_ / 128), 256>>>(w2, b2, out);
}

// round 11
// speedup vs baseline: 1.5230x; 1.4171x over previous
#include <cuda_runtime.h>
#include <cuda_fp16.h>
#include <cstdint>

// ---------------- problem constants ----------------
#define B_        8
#define S_        1024
#define D_        4096
#define DV_       1024
#define IMG_      336
#define PATCH_    14
#define GRID_     24
#define NP_       576
#define MAXE_     1599
#define KPATCH_   588
#define M_        (B_*NP_)    // 4608
#define IMAGE_TOKEN_ 32000

#define OFF_EMB   1LL
#define N_EMB     ((long long)B_*MAXE_*D_)
#define OFF_ATTN  (OFF_EMB + N_EMB)
#define OFF_LAB   (OFF_ATTN + (long long)B_*MAXE_)
#define OFF_ROUT  (OFF_LAB  + (long long)B_*MAXE_)
#define N_TAIL    (32LL*MAXE_*8 + 32LL*MAXE_*2)

// ---------------- device scratch (fp32 only — validated pattern) ----------------
__device__ float g_h[(size_t)M_ * DV_];   // patch-embed output
__device__ float g_g[(size_t)M_ * D_];    // gelu output
__device__ int   g_spos[B_];

__device__ __forceinline__ float gelu_tanh(float x) {
    float x3 = x * x * x;
    return 0.5f * x * (1.0f + tanhf(0.7978845608028654f * (x + 0.044715f * x3)));
}

__device__ __forceinline__ uint32_t s2u(const void* p) {
    return (uint32_t)__cvta_generic_to_shared(p);
}
__device__ __forceinline__ void ldmx4(uint32_t* r, uint32_t addr) {
    asm volatile("ldmatrix.sync.aligned.m8n8.x4.shared.b16 {%0,%1,%2,%3}, [%4];"
                 : "=r"(r[0]), "=r"(r[1]), "=r"(r[2]), "=r"(r[3]) : "r"(addr) : "memory");
}
__device__ __forceinline__ void ldmx4t(uint32_t* r, uint32_t addr) {
    asm volatile("ldmatrix.sync.aligned.m8n8.x4.trans.shared.b16 {%0,%1,%2,%3}, [%4];"
                 : "=r"(r[0]), "=r"(r[1]), "=r"(r[2]), "=r"(r[3]) : "r"(addr) : "memory");
}
__device__ __forceinline__ void mma_f16(float* c, const uint32_t* a, const uint32_t* b) {
    asm volatile(
        "mma.sync.aligned.m16n8k16.row.col.f32.f16.f16.f32 "
        "{%0,%1,%2,%3}, {%4,%5,%6,%7}, {%8,%9}, {%0,%1,%2,%3};"
        : "+f"(c[0]), "+f"(c[1]), "+f"(c[2]), "+f"(c[3])
        : "r"(a[0]), "r"(a[1]), "r"(a[2]), "r"(a[3]), "r"(b[0]), "r"(b[1]));
}
__device__ __forceinline__ uint32_t ph(int row) { return ((row >> 2) & 1) << 4; }

// pack 8 fp32 -> 8 fp16 (one uint4)
__device__ __forceinline__ uint4 cvt8h(const float* f) {
    __half2 a = __floats2half2_rn(f[0], f[1]);
    __half2 b = __floats2half2_rn(f[2], f[3]);
    __half2 c = __floats2half2_rn(f[4], f[5]);
    __half2 d = __floats2half2_rn(f[6], f[7]);
    return make_uint4(*(uint32_t*)&a, *(uint32_t*)&b, *(uint32_t*)&c, *(uint32_t*)&d);
}

// ---------------- small kernels (R1-proven) ----------------
__global__ void k_fill(float* __restrict__ out) {
    long long i = (long long)blockIdx.x * blockDim.x + threadIdx.x;
    if (i == 0) out[0] = 0.0f;
    if (i < B_) g_spos[i] = S_;
    long long stride = (long long)gridDim.x * blockDim.x;
    for (long long j = i; j < N_TAIL; j += stride)
        out[OFF_ROUT + j] = 0.0f;
}

__global__ void k_spos(const int* __restrict__ ids) {
    int i = blockIdx.x * blockDim.x + threadIdx.x;
    if (i < B_ * S_ && ids[i] == IMAGE_TOKEN_)
        atomicMin(&g_spos[i / S_], i % S_);
}

__global__ void k_text(const int* __restrict__ ids, const int* __restrict__ mask,
                       const int* __restrict__ labels, const float* __restrict__ table,
                       float* __restrict__ out) {
    int bs = blockIdx.x;
    int b = bs / S_, s = bs - b * S_;
    int id = ids[bs];
    if (id == IMAGE_TOKEN_) return;
    int sp = g_spos[b];
    int dest = s + (s > sp ? (NP_ - 1) : 0);
    const float* __restrict__ src = table + (long long)id * D_;
    float* __restrict__ dst = out + OFF_EMB + ((long long)b * MAXE_ + dest) * D_;
    for (int j = threadIdx.x; j < D_; j += blockDim.x)
        dst[j] = src[j];
    if (threadIdx.x == 0) {
        out[OFF_ATTN + (long long)b * MAXE_ + dest] = (float)mask[bs];
        out[OFF_LAB  + (long long)b * MAXE_ + dest] = (float)labels[bs];
    }
}

__global__ void k_imgmeta(float* __restrict__ out) {
    int i = blockIdx.x * blockDim.x + threadIdx.x;
    if (i >= B_ * NP_) return;
    int b = i / NP_, t = i - b * NP_;
    int dest = g_spos[b] + t;
    out[OFF_ATTN + (long long)b * MAXE_ + dest] = 1.0f;
    out[OFF_LAB  + (long long)b * MAXE_ + dest] = -100.0f;
}

// ---------------- patch-embed GEMM (R1-proven, fp32) ----------------
__global__ void __launch_bounds__(256)
k_patch(const float* __restrict__ pix, const float* __restrict__ Bw,
        const float* __restrict__ bias) {
    __shared__ float As[16][132];
    __shared__ float Bs[16][132];
    int t  = threadIdx.x;
    int m0 = blockIdx.y * 128;
    int n0 = blockIdx.x * 128;
    float acc[8][8] = {};
    int brow = t >> 5, bcol = t & 31;
    int rm = (t >> 4) * 8, rn = (t & 15) * 8;

    for (int k0 = 0; k0 < KPATCH_; k0 += 16) {
        #pragma unroll
        for (int i = 0; i < 8; i++) {
            int idx = t + 256 * i;
            int r  = idx >> 4;
            int kk = idx & 15;
            int k  = k0 + kk;
            float v = 0.0f;
            if (k < KPATCH_) {
                int m  = m0 + r;
                int ni = m / NP_;
                int tt = m - ni * NP_;
                int gi = tt / GRID_, gj = tt - gi * GRID_;
                int c  = k / 196;
                int rem = k - c * 196;
                int pi = rem / PATCH_, pj = rem - pi * PATCH_;
                long long addr = (((long long)ni * 3 + c) * IMG_ + gi * PATCH_ + pi) * IMG_
                               + gj * PATCH_ + pj;
                v = pix[addr];
            }
            As[kk][r] = v;
        }
        #pragma unroll
        for (int i = 0; i < 2; i++) {
            int kk = brow + i * 8;
            int k  = k0 + kk;
            float4 v = make_float4(0.f, 0.f, 0.f, 0.f);
            if (k < KPATCH_)
                v = *(const float4*)(Bw + (long long)k * DV_ + n0 + bcol * 4);
            *(float4*)(&Bs[kk][bcol * 4]) = v;
        }
        __syncthreads();
        #pragma unroll
        for (int k = 0; k < 16; k++) {
            float ra[8], rb[8];
            #pragma unroll
            for (int i = 0; i < 8; i++) ra[i] = As[k][rm + i];
            #pragma unroll
            for (int j = 0; j < 8; j++) rb[j] = Bs[k][rn + j];
            #pragma unroll
            for (int i = 0; i < 8; i++)
                #pragma unroll
                for (int j = 0; j < 8; j++)
                    acc[i][j] += ra[i] * rb[j];
        }
        __syncthreads();
    }
    #pragma unroll
    for (int i = 0; i < 8; i++) {
        int m = m0 + rm + i;
        #pragma unroll
        for (int j = 0; j < 8; j++) {
            int n = n0 + rn + j;
            g_h[(size_t)m * DV_ + n] = acc[i][j] + bias[n];
        }
    }
}

// ---------------- TC GEMM — pure fp16 HMMA (R8-proven pipeline, 1 term) ----------------
// fp32 sources, in-kernel fp16 cvt (same 2^-11 rounding as the tf32 run that
// measured rel_err 4.1e-4), plain global loads, 12KB static smem, register prefetch.
// CTA 128(M) x 256(N), K-chunk 16, 8 warps 2x4, warp tile 64x64, mma.m16n8k16.f16.
template<int EPI>
__global__ void __launch_bounds__(256)
k_tc(const float* __restrict__ W, const float* __restrict__ bias,
     float* __restrict__ out) {
    constexpr int K = (EPI == 1) ? DV_ : D_;
    const float* __restrict__ A = (EPI == 1) ? g_h : g_g;

    __shared__ __align__(16) char sa[4096];   // A: 128 rows x 32B (phase swizzle)
    __shared__ __align__(16) char sb[8192];   // B: 16 k-rows x 512B (XOR k swizzle)

    const int t = threadIdx.x, l = t & 31, wid = t >> 5;
    const int wm = wid >> 2, wn = wid & 3;
    const int m0 = blockIdx.y * 128;
    const int n0 = blockIdx.x * 256;

    float acc[4][8][4] = {};

    // register staging (R8-proven shape)
    const int arow = t >> 1, ahalf = t & 1;
    float ra[8], rb[2][8];

    auto ldregs = [&](int kc) {
        const float* ap = A + (size_t)(m0 + arow) * K + kc + ahalf * 8;
        float4 x = *(const float4*)ap;
        float4 y = *(const float4*)(ap + 4);
        ra[0]=x.x; ra[1]=x.y; ra[2]=x.z; ra[3]=x.w;
        ra[4]=y.x; ra[5]=y.y; ra[6]=y.z; ra[7]=y.w;
        #pragma unroll
        for (int i = 0; i < 2; i++) {
            int idx = t + 256 * i;
            int k = idx >> 5, seg = idx & 31;
            const float* bp = W + (size_t)(kc + k) * D_ + n0 + seg * 8;
            float4 u = *(const float4*)bp;
            float4 v = *(const float4*)(bp + 4);
            rb[i][0]=u.x; rb[i][1]=u.y; rb[i][2]=u.z; rb[i][3]=u.w;
            rb[i][4]=v.x; rb[i][5]=v.y; rb[i][6]=v.z; rb[i][7]=v.w;
        }
    };
    auto stregs = [&]() {
        uint32_t off = arow * 32 + ((ahalf * 16) ^ ph(arow));
        *(uint4*)(sa + off) = cvt8h(ra);
        #pragma unroll
        for (int i = 0; i < 2; i++) {
            int idx = t + 256 * i;
            int k = idx >> 5, seg = idx & 31;
            uint32_t o2 = k * 512 + ((seg * 16) ^ ((k & 7) * 16));
            *(uint4*)(sb + o2) = cvt8h(rb[i]);
        }
    };

    const int frow = l & 15, kb = ((l >> 4) & 1) * 16;
    const int bg = l >> 3, br = l & 7;
    const int bk = (bg & 1) * 8 + br;
    const int bnb = (bg >> 1) * 8;

    auto compute = [&]() {
        uint32_t ah[4][4];
        #pragma unroll
        for (int mi = 0; mi < 4; mi++) {
            int row = wm * 64 + mi * 16 + frow;
            uint32_t off = row * 32 + (kb ^ ph(row));
            ldmx4(ah[mi], s2u(sa) + off);
        }
        #pragma unroll
        for (int p = 0; p < 4; p++) {
            int nb = wn * 64 + p * 16 + bnb;
            uint32_t o = bk * 512 + ((nb * 2) ^ ((bk & 7) * 16));
            uint32_t rh[4];
            ldmx4t(rh, s2u(sb) + o);
            uint32_t b0[2] = { rh[0], rh[1] }, b1[2] = { rh[2], rh[3] };
            #pragma unroll
            for (int mi = 0; mi < 4; mi++) {
                mma_f16(acc[mi][2*p],   ah[mi], b0);
                mma_f16(acc[mi][2*p+1], ah[mi], b1);
            }
        }
    };

    const int nch = K / 16;
    ldregs(0);
    for (int c = 0; c < nch; c++) {
        stregs();
        __syncthreads();
        if (c + 1 < nch) ldregs((c + 1) * 16);
        compute();
        __syncthreads();
    }

    // epilogue — EPI==2 rows start at OFF_EMB=1 (odd float offset): scalar stores only.
    const int lrow = l >> 2, lcol = (l & 3) * 2;
    #pragma unroll
    for (int mi = 0; mi < 4; mi++) {
        #pragma unroll
        for (int part = 0; part < 2; part++) {
            int m = m0 + wm * 64 + mi * 16 + lrow + part * 8;
            long long rowbase;
            if (EPI == 2) {
                int bb = m / NP_;
                int tt = m - bb * NP_;
                rowbase = OFF_EMB + ((long long)bb * MAXE_ + g_spos[bb] + tt) * (long long)D_;
            } else {
                rowbase = (long long)m * D_;
            }
            #pragma unroll
            for (int nj = 0; nj < 8; nj++) {
                int n = n0 + wn * 64 + nj * 8 + lcol;
                float v0 = acc[mi][nj][part * 2 + 0] + bias[n];
                float v1 = acc[mi][nj][part * 2 + 1] + bias[n + 1];
                if (EPI == 1) {
                    float2 gg = make_float2(gelu_tanh(v0), gelu_tanh(v1));
                    *(float2*)&g_g[rowbase + n] = gg;
                } else {
                    out[rowbase + n]     = v0;
                    out[rowbase + n + 1] = v1;
                }
            }
        }
    }
}

// ---------------- launch ----------------
extern "C" void kernel_launch(void* const* d_in, const int* in_sizes, int n_in,
                              void* d_out, int out_size) {
    const int*   ids     = (const int*)  d_in[0];
    const float* pix     = (const float*)d_in[1];
    const int*   mask    = (const int*)  d_in[2];
    const int*   labels  = (const int*)  d_in[3];
    const float* table   = (const float*)d_in[4];
    const float* patch_w = (const float*)d_in[6];
    const float* patch_b = (const float*)d_in[7];
    const float* w1      = (const float*)d_in[8];
    const float* b1      = (const float*)d_in[9];
    const float* w2      = (const float*)d_in[10];
    const float* b2      = (const float*)d_in[11];
    float* out = (float*)d_out;

    k_fill<<<512, 256>>>(out);
    k_spos<<<(B_ * S_ + 255) / 256, 256>>>(ids);
    k_text<<<B_ * S_, 256>>>(ids, mask, labels, table, out);
    k_imgmeta<<<(B_ * NP_ + 255) / 256, 256>>>(out);

    k_patch<<<dim3(DV_ / 128, M_ / 128), 256>>>(pix, patch_w, patch_b);
    k_tc<1><<<dim3(D_ / 256, M_ / 128), 256>>>(w1, b1, out);
    k_tc<2><<<dim3(D_ / 256, M_ / 128), 256>>>(w2, b2, out);
}

// round 12
// speedup vs baseline: 2.2257x; 1.4614x over previous
#include <cuda_runtime.h>
#include <cuda_fp16.h>
#include <cstdint>

// ---------------- problem constants ----------------
#define B_        8
#define S_        1024
#define D_        4096
#define DV_       1024
#define IMG_      336
#define PATCH_    14
#define GRID_     24
#define NP_       576
#define MAXE_     1599
#define KPATCH_   588
#define M_        (B_*NP_)    // 4608
#define IMAGE_TOKEN_ 32000

#define OFF_EMB   1LL
#define N_EMB     ((long long)B_*MAXE_*D_)
#define OFF_ATTN  (OFF_EMB + N_EMB)
#define OFF_LAB   (OFF_ATTN + (long long)B_*MAXE_)
#define OFF_ROUT  (OFF_LAB  + (long long)B_*MAXE_)
#define N_TAIL    (32LL*MAXE_*8 + 32LL*MAXE_*2)

// ---------------- device scratch ----------------
__device__ __half g_hH[(size_t)M_ * DV_];    // patch-embed output (fp16)
__device__ __half g_gH[(size_t)M_ * D_];     // gelu output (fp16)
__device__ __half g_w1H[(size_t)DV_ * D_];   // w1 fp16, same [k][n] layout
__device__ __half g_w2H[(size_t)D_ * D_];    // w2 fp16, same [k][n] layout
__device__ int    g_spos[B_];

__device__ __forceinline__ float gelu_tanh(float x) {
    float x3 = x * x * x;
    return 0.5f * x * (1.0f + tanhf(0.7978845608028654f * (x + 0.044715f * x3)));
}

__device__ __forceinline__ uint32_t s2u(const void* p) {
    return (uint32_t)__cvta_generic_to_shared(p);
}
__device__ __forceinline__ void ldmx4(uint32_t* r, uint32_t addr) {
    asm volatile("ldmatrix.sync.aligned.m8n8.x4.shared.b16 {%0,%1,%2,%3}, [%4];"
                 : "=r"(r[0]), "=r"(r[1]), "=r"(r[2]), "=r"(r[3]) : "r"(addr) : "memory");
}
__device__ __forceinline__ void ldmx4t(uint32_t* r, uint32_t addr) {
    asm volatile("ldmatrix.sync.aligned.m8n8.x4.trans.shared.b16 {%0,%1,%2,%3}, [%4];"
                 : "=r"(r[0]), "=r"(r[1]), "=r"(r[2]), "=r"(r[3]) : "r"(addr) : "memory");
}
__device__ __forceinline__ void mma_f16(float* c, const uint32_t* a, const uint32_t* b) {
    asm volatile(
        "mma.sync.aligned.m16n8k16.row.col.f32.f16.f16.f32 "
        "{%0,%1,%2,%3}, {%4,%5,%6,%7}, {%8,%9}, {%0,%1,%2,%3};"
        : "+f"(c[0]), "+f"(c[1]), "+f"(c[2]), "+f"(c[3])
        : "r"(a[0]), "r"(a[1]), "r"(a[2]), "r"(a[3]), "r"(b[0]), "r"(b[1]));
}

// ---------------- small kernels (R1-proven) ----------------
__global__ void k_fill(float* __restrict__ out) {
    long long i = (long long)blockIdx.x * blockDim.x + threadIdx.x;
    if (i == 0) out[0] = 0.0f;
    if (i < B_) g_spos[i] = S_;
    long long stride = (long long)gridDim.x * blockDim.x;
    for (long long j = i; j < N_TAIL; j += stride)
        out[OFF_ROUT + j] = 0.0f;
}

__global__ void k_spos(const int* __restrict__ ids) {
    int i = blockIdx.x * blockDim.x + threadIdx.x;
    if (i < B_ * S_ && ids[i] == IMAGE_TOKEN_)
        atomicMin(&g_spos[i / S_], i % S_);
}

__global__ void k_text(const int* __restrict__ ids, const int* __restrict__ mask,
                       const int* __restrict__ labels, const float* __restrict__ table,
                       float* __restrict__ out) {
    int bs = blockIdx.x;
    int b = bs / S_, s = bs - b * S_;
    int id = ids[bs];
    if (id == IMAGE_TOKEN_) return;
    int sp = g_spos[b];
    int dest = s + (s > sp ? (NP_ - 1) : 0);
    const float* __restrict__ src = table + (long long)id * D_;
    float* __restrict__ dst = out + OFF_EMB + ((long long)b * MAXE_ + dest) * D_;
    for (int j = threadIdx.x; j < D_; j += blockDim.x)
        dst[j] = src[j];
    if (threadIdx.x == 0) {
        out[OFF_ATTN + (long long)b * MAXE_ + dest] = (float)mask[bs];
        out[OFF_LAB  + (long long)b * MAXE_ + dest] = (float)labels[bs];
    }
}

__global__ void k_imgmeta(float* __restrict__ out) {
    int i = blockIdx.x * blockDim.x + threadIdx.x;
    if (i >= B_ * NP_) return;
    int b = i / NP_, t = i - b * NP_;
    int dest = g_spos[b] + t;
    out[OFF_ATTN + (long long)b * MAXE_ + dest] = 1.0f;
    out[OFF_LAB  + (long long)b * MAXE_ + dest] = -100.0f;
}

// ---------------- fp32 -> fp16 weight conversion (elementwise) ----------------
__global__ void k_convh(const float* __restrict__ src, __half* __restrict__ dst, int n4) {
    int i = blockIdx.x * blockDim.x + threadIdx.x;
    long long stride = (long long)gridDim.x * blockDim.x;
    for (long long j = i; j < n4; j += stride) {
        float4 v = *(const float4*)(src + j * 4);
        __half2 a = __floats2half2_rn(v.x, v.y);
        __half2 b = __floats2half2_rn(v.z, v.w);
        uint2 pk = make_uint2(*(uint32_t*)&a, *(uint32_t*)&b);
        *(uint2*)(dst + j * 4) = pk;
    }
}

// ---------------- patch-embed GEMM (R1-proven math, fp16 output) ----------------
__global__ void __launch_bounds__(256)
k_patch(const float* __restrict__ pix, const float* __restrict__ Bw,
        const float* __restrict__ bias) {
    __shared__ float As[16][132];
    __shared__ float Bs[16][132];
    int t  = threadIdx.x;
    int m0 = blockIdx.y * 128;
    int n0 = blockIdx.x * 128;
    float acc[8][8] = {};
    int brow = t >> 5, bcol = t & 31;
    int rm = (t >> 4) * 8, rn = (t & 15) * 8;

    for (int k0 = 0; k0 < KPATCH_; k0 += 16) {
        #pragma unroll
        for (int i = 0; i < 8; i++) {
            int idx = t + 256 * i;
            int r  = idx >> 4;
            int kk = idx & 15;
            int k  = k0 + kk;
            float v = 0.0f;
            if (k < KPATCH_) {
                int m  = m0 + r;
                int ni = m / NP_;
                int tt = m - ni * NP_;
                int gi = tt / GRID_, gj = tt - gi * GRID_;
                int c  = k / 196;
                int rem = k - c * 196;
                int pi = rem / PATCH_, pj = rem - pi * PATCH_;
                long long addr = (((long long)ni * 3 + c) * IMG_ + gi * PATCH_ + pi) * IMG_
                               + gj * PATCH_ + pj;
                v = pix[addr];
            }
            As[kk][r] = v;
        }
        #pragma unroll
        for (int i = 0; i < 2; i++) {
            int kk = brow + i * 8;
            int k  = k0 + kk;
            float4 v = make_float4(0.f, 0.f, 0.f, 0.f);
            if (k < KPATCH_)
                v = *(const float4*)(Bw + (long long)k * DV_ + n0 + bcol * 4);
            *(float4*)(&Bs[kk][bcol * 4]) = v;
        }
        __syncthreads();
        #pragma unroll
        for (int k = 0; k < 16; k++) {
            float ra[8], rb[8];
            #pragma unroll
            for (int i = 0; i < 8; i++) ra[i] = As[k][rm + i];
            #pragma unroll
            for (int j = 0; j < 8; j++) rb[j] = Bs[k][rn + j];
            #pragma unroll
            for (int i = 0; i < 8; i++)
                #pragma unroll
                for (int j = 0; j < 8; j++)
                    acc[i][j] += ra[i] * rb[j];
        }
        __syncthreads();
    }
    #pragma unroll
    for (int i = 0; i < 8; i++) {
        int m = m0 + rm + i;
        #pragma unroll
        for (int j = 0; j < 8; j++) {
            int n = n0 + rn + j;
            g_hH[(size_t)m * DV_ + n] = __float2half(acc[i][j] + bias[n]);
        }
    }
}

// ---------------- TC GEMM — fp16-resident operands, K-chunk 32 ----------------
// fp16 global sources (no cvt in loop), 24KB static smem, register prefetch,
// R11-proven pipeline shape. CTA 128(M) x 256(N), 8 warps 2x4, warp tile 64x64.
// A smem: 128 rows x 64B, XOR key ((row>>1)&3)<<4 (bank-verified for STS.128 + ldmatrix).
// B smem: 32 k-rows x 512B, XOR key (k&7)*16 (R8/R11-proven pattern).
template<int EPI>
__global__ void __launch_bounds__(256)
k_tc(const float* __restrict__ bias, float* __restrict__ out) {
    constexpr int K = (EPI == 1) ? DV_ : D_;
    const __half* __restrict__ A  = (EPI == 1) ? g_hH : g_gH;
    const __half* __restrict__ WH = (EPI == 1) ? g_w1H : g_w2H;

    __shared__ __align__(16) char sa[8192];    // 128 rows x 64B
    __shared__ __align__(16) char sb[16384];   // 32 k-rows x 512B

    const int t = threadIdx.x, l = t & 31, wid = t >> 5;
    const int wm = wid >> 2, wn = wid & 3;
    const int m0 = blockIdx.y * 128;
    const int n0 = blockIdx.x * 256;

    float acc[4][8][4] = {};

    // register staging: A 2 x uint4, B 4 x uint4 per thread
    uint4 ra[2], rb[4];

    auto ldregs = [&](int kc) {
        #pragma unroll
        for (int i = 0; i < 2; i++) {
            int idx = t + 256 * i;
            int row = idx >> 2, seg = idx & 3;
            ra[i] = *(const uint4*)(A + (size_t)(m0 + row) * K + kc + seg * 8);
        }
        #pragma unroll
        for (int i = 0; i < 4; i++) {
            int idx = t + 256 * i;
            int k = idx >> 5, seg = idx & 31;
            rb[i] = *(const uint4*)(WH + (size_t)(kc + k) * D_ + n0 + seg * 8);
        }
    };
    auto stregs = [&]() {
        #pragma unroll
        for (int i = 0; i < 2; i++) {
            int idx = t + 256 * i;
            int row = idx >> 2, seg = idx & 3;
            uint32_t off = row * 64 + ((seg * 16) ^ (((row >> 1) & 3) << 4));
            *(uint4*)(sa + off) = ra[i];
        }
        #pragma unroll
        for (int i = 0; i < 4; i++) {
            int idx = t + 256 * i;
            int k = idx >> 5, seg = idx & 31;
            uint32_t off = k * 512 + ((seg * 16) ^ ((k & 7) * 16));
            *(uint4*)(sb + off) = rb[i];
        }
    };

    const int frow = l & 15, kb = ((l >> 4) & 1) * 16;
    const int bg = l >> 3, br = l & 7;
    const int bk = (bg & 1) * 8 + br;
    const int bnb = (bg >> 1) * 8;

    auto compute = [&]() {
        #pragma unroll
        for (int ks = 0; ks < 2; ks++) {
            uint32_t ah[4][4];
            #pragma unroll
            for (int mi = 0; mi < 4; mi++) {
                int row = wm * 64 + mi * 16 + frow;
                uint32_t off = row * 64 + ((ks * 32 + kb) ^ (((row >> 1) & 3) << 4));
                ldmx4(ah[mi], s2u(sa) + off);
            }
            #pragma unroll
            for (int p = 0; p < 4; p++) {
                int nb = wn * 64 + p * 16 + bnb;
                int kr = ks * 16 + bk;
                uint32_t o = kr * 512 + ((nb * 2) ^ ((bk & 7) * 16));
                uint32_t rh[4];
                ldmx4t(rh, s2u(sb) + o);
                uint32_t b0[2] = { rh[0], rh[1] }, b1[2] = { rh[2], rh[3] };
                #pragma unroll
                for (int mi = 0; mi < 4; mi++) {
                    mma_f16(acc[mi][2*p],   ah[mi], b0);
                    mma_f16(acc[mi][2*p+1], ah[mi], b1);
                }
            }
        }
    };

    const int nch = K / 32;
    ldregs(0);
    for (int c = 0; c < nch; c++) {
        stregs();
        __syncthreads();
        if (c + 1 < nch) ldregs((c + 1) * 32);
        compute();
        __syncthreads();
    }

    // epilogue — EPI==2 rows start at OFF_EMB=1 (odd float offset): scalar stores only.
    const int lrow = l >> 2, lcol = (l & 3) * 2;
    #pragma unroll
    for (int mi = 0; mi < 4; mi++) {
        #pragma unroll
        for (int part = 0; part < 2; part++) {
            int m = m0 + wm * 64 + mi * 16 + lrow + part * 8;
            long long rowbase;
            if (EPI == 2) {
                int bb = m / NP_;
                int tt = m - bb * NP_;
                rowbase = OFF_EMB + ((long long)bb * MAXE_ + g_spos[bb] + tt) * (long long)D_;
            } else {
                rowbase = (long long)m * D_;
            }
            #pragma unroll
            for (int nj = 0; nj < 8; nj++) {
                int n = n0 + wn * 64 + nj * 8 + lcol;
                float v0 = acc[mi][nj][part * 2 + 0] + bias[n];
                float v1 = acc[mi][nj][part * 2 + 1] + bias[n + 1];
                if (EPI == 1) {
                    __half2 hh = __floats2half2_rn(gelu_tanh(v0), gelu_tanh(v1));
                    *(__half2*)&g_gH[rowbase + n] = hh;
                } else {
                    out[rowbase + n]     = v0;
                    out[rowbase + n + 1] = v1;
                }
            }
        }
    }
}

// ---------------- launch ----------------
extern "C" void kernel_launch(void* const* d_in, const int* in_sizes, int n_in,
                              void* d_out, int out_size) {
    const int*   ids     = (const int*)  d_in[0];
    const float* pix     = (const float*)d_in[1];
    const int*   mask    = (const int*)  d_in[2];
    const int*   labels  = (const int*)  d_in[3];
    const float* table   = (const float*)d_in[4];
    const float* patch_w = (const float*)d_in[6];
    const float* patch_b = (const float*)d_in[7];
    const float* w1      = (const float*)d_in[8];
    const float* b1      = (const float*)d_in[9];
    const float* w2      = (const float*)d_in[10];
    const float* b2      = (const float*)d_in[11];
    float* out = (float*)d_out;

    __half *w1H, *w2H;
    cudaGetSymbolAddress((void**)&w1H, g_w1H);
    cudaGetSymbolAddress((void**)&w2H, g_w2H);

    k_fill<<<512, 256>>>(out);
    k_spos<<<(B_ * S_ + 255) / 256, 256>>>(ids);
    k_text<<<B_ * S_, 256>>>(ids, mask, labels, table, out);
    k_imgmeta<<<(B_ * NP_ + 255) / 256, 256>>>(out);

    k_convh<<<2048, 256>>>(w1, w1H, (DV_ * D_) / 4);
    k_convh<<<8192, 256>>>(w2, w2H, (D_ * D_) / 4);

    k_patch<<<dim3(DV_ / 128, M_ / 128), 256>>>(pix, patch_w, patch_b);
    k_tc<1><<<dim3(D_ / 256, M_ / 128), 256>>>(b1, out);
    k_tc<2><<<dim3(D_ / 256, M_ / 128), 256>>>(b2, out);
}